// round 8
// baseline (speedup 1.0000x reference)
#include <cuda_runtime.h>
#include <cuda_bf16.h>
#include <stdint.h>
#include <math.h>

#define B_    64
#define T_    8192
#define DIN   20
#define NROWS ((size_t)B_ * T_)
#define WARM  512
#define NTILES 4096
#define NBLK   148

// device scratch
__device__ float g_gate[NROWS];
__device__ float g_qf[NROWS];
__device__ float g_qs[NROWS];
// pre-split weight planes (bf16 hi/lo), padded layouts
// W1^T: [n=128][k=24]   W2^T: [n=128][k=136]
__device__ __align__(16) __nv_bfloat16 g_w1h[128 * 24];
__device__ __align__(16) __nv_bfloat16 g_w1l[128 * 24];
__device__ __align__(16) __nv_bfloat16 g_w2h[128 * 136];
__device__ __align__(16) __nv_bfloat16 g_w2l[128 * 136];

// ---------------------------------------------------------------------------
__device__ __forceinline__ void mma16(float* d, const uint32_t* a, const uint32_t* b) {
    asm volatile(
        "mma.sync.aligned.m16n8k16.row.col.f32.bf16.bf16.f32 "
        "{%0,%1,%2,%3}, {%4,%5,%6,%7}, {%8,%9}, {%0,%1,%2,%3};"
        : "+f"(d[0]), "+f"(d[1]), "+f"(d[2]), "+f"(d[3])
        : "r"(a[0]), "r"(a[1]), "r"(a[2]), "r"(a[3]), "r"(b[0]), "r"(b[1]));
}
__device__ __forceinline__ void mma8b(float* d, const uint32_t* a, const uint32_t* b) {
    asm volatile(
        "mma.sync.aligned.m16n8k8.row.col.f32.bf16.bf16.f32 "
        "{%0,%1,%2,%3}, {%4,%5}, {%6}, {%0,%1,%2,%3};"
        : "+f"(d[0]), "+f"(d[1]), "+f"(d[2]), "+f"(d[3])
        : "r"(a[0]), "r"(a[1]), "r"(b[0]));
}
__device__ __forceinline__ void ldsm4(uint32_t* R, uint32_t addr) {
    asm volatile("ldmatrix.sync.aligned.m8n8.x4.shared.b16 {%0,%1,%2,%3},[%4];"
        : "=r"(R[0]), "=r"(R[1]), "=r"(R[2]), "=r"(R[3]) : "r"(addr));
}
__device__ __forceinline__ void ldsm2(uint32_t* R, uint32_t addr) {
    asm volatile("ldmatrix.sync.aligned.m8n8.x2.shared.b16 {%0,%1},[%2];"
        : "=r"(R[0]), "=r"(R[1]) : "r"(addr));
}
__device__ __forceinline__ void ldsm1(uint32_t* R, uint32_t addr) {
    asm volatile("ldmatrix.sync.aligned.m8n8.x1.shared.b16 {%0},[%1];"
        : "=r"(R[0]) : "r"(addr));
}
__device__ __forceinline__ void cpasync16(uint32_t saddr, const void* g) {
    asm volatile("cp.async.cg.shared.global [%0], [%1], 16;" :: "r"(saddr), "l"(g));
}
__device__ __forceinline__ float gelu_exact(float x) {
    return 0.5f * x * (1.0f + erff(x * 0.70710678118654752f));
}
__device__ __forceinline__ void split2_bf16(float x0, float x1,
                                            uint32_t& hi, uint32_t& lo) {
    uint32_t h;
    asm("cvt.rn.bf16x2.f32 %0, %1, %2;" : "=r"(h) : "f"(x1), "f"(x0));
    float h0 = __uint_as_float(h << 16);
    float h1 = __uint_as_float(h & 0xffff0000u);
    float r0 = x0 - h0, r1 = x1 - h1;
    asm("cvt.rn.bf16x2.f32 %0, %1, %2;" : "=r"(lo) : "f"(r1), "f"(r0));
    hi = h;
}

// ---------------------------------------------------------------------------
// Kernel A: gate + EMA + (blocks 0..95) weight pre-split.
// ---------------------------------------------------------------------------
__global__ void __launch_bounds__(256) ema_kernel(
    const float* __restrict__ gaze,
    const float* __restrict__ p_logthr, const float* __restrict__ p_invT,
    const float* __restrict__ W1, const float* __restrict__ W2,
    float* __restrict__ gate_o, float* __restrict__ qf_o, float* __restrict__ qs_o)
{
    extern __shared__ float sm[];
    float2* sg  = reinterpret_cast<float2*>(sm);
    float*  sga = sm + 5124;
    float*  sqf = sga + 2560;
    float*  sqs = sqf + 2560;
    float*  scn = sqs + 2560;

    const int tid = threadIdx.x;

    // ---- folded weight prep (independent of EMA work) ----
    {
        int i = blockIdx.x * 256 + tid;
        if (i < 128 * 136) {
            int n = i / 136, k = i - n * 136;
            float v = (k < 128) ? W2[k * 128 + n] : 0.0f;
            __nv_bfloat16 h = __float2bfloat16_rn(v);
            g_w2h[i] = h;
            g_w2l[i] = __float2bfloat16_rn(v - __bfloat162float(h));
        }
        if (i < 128 * 24) {
            int n = i / 24, k = i - n * 24;
            float v = (k < DIN) ? W1[k * 128 + n] : 0.0f;
            __nv_bfloat16 h = __float2bfloat16_rn(v);
            g_w1h[i] = h;
            g_w1l[i] = __float2bfloat16_rn(v - __bfloat162float(h));
        }
    }

    const int row = blockIdx.x >> 2;
    const int t0  = (blockIdx.x & 3) * 2048;
    const int ts  = max(t0 - WARM, 0);
    const int ts2 = max(ts - 1, 0);
    const int E   = t0 + 2048 - ts;
    const int NG  = t0 + 2048 - ts2;
    const int hof = ts - ts2;

    const float2* gz = reinterpret_cast<const float2*>(gaze) + (size_t)row * T_;
    for (int i = tid; i < NG; i += 256) sg[i] = gz[ts2 + i];
    const float thr  = expf(p_logthr[0]);
    const float invT = p_invT[0];
    const float inv_dt = 240.0f;
    __syncthreads();

    const int CH = (E + 255) >> 8;
    float Af = 1.0f, Bf = 0.0f, As = 1.0f, Bs = 0.0f;
    for (int i = 0; i < CH; i++) {
        int e = tid * CH + i;
        if (e < E) {
            int j = e + hof;
            float2 xc = sg[j];
            float2 x1 = sg[max(j - 1, 0)];
            float vx = (xc.x - x1.x) * inv_dt;
            float vy = (xc.y - x1.y) * inv_dt;
            float sp = sqrtf(vx * vx + vy * vy);
            float g  = 1.0f / (1.0f + expf(-invT * (sp - thr)));
            sga[e] = g;
            Bf = 0.8f  * Bf + 0.2f  * g;  Af *= 0.8f;
            Bs = 0.95f * Bs + 0.05f * g;  As *= 0.95f;
        }
    }
    const unsigned full = 0xffffffffu;
    const int lane = tid & 31, warp = tid >> 5;
    float iAf = Af, iBf = Bf, iAs = As, iBs = Bs;
#pragma unroll
    for (int d = 1; d < 32; d <<= 1) {
        float pa = __shfl_up_sync(full, iAf, d);
        float pb = __shfl_up_sync(full, iBf, d);
        float qa = __shfl_up_sync(full, iAs, d);
        float qb = __shfl_up_sync(full, iBs, d);
        if (lane >= d) {
            iBf = iAf * pb + iBf;  iAf *= pa;
            iBs = iAs * qb + iBs;  iAs *= qa;
        }
    }
    float eAf = __shfl_up_sync(full, iAf, 1), eBf = __shfl_up_sync(full, iBf, 1);
    float eAs = __shfl_up_sync(full, iAs, 1), eBs = __shfl_up_sync(full, iBs, 1);
    if (lane == 0) { eAf = 1.0f; eBf = 0.0f; eAs = 1.0f; eBs = 0.0f; }
    if (lane == 31) {
        scn[warp] = iAf; scn[8 + warp] = iBf; scn[16 + warp] = iAs; scn[24 + warp] = iBs;
    }
    __syncthreads();
    float pBf = 0.0f, pBs = 0.0f;
    for (int w = 0; w < warp; w++) {
        pBf = scn[w] * pBf + scn[8 + w];
        pBs = scn[16 + w] * pBs + scn[24 + w];
    }
    float accf = eAf * pBf + eBf;
    float accs = eAs * pBs + eBs;
    for (int i = 0; i < CH; i++) {
        int e = tid * CH + i;
        if (e < E) {
            float g = sga[e];
            accf = 0.8f  * accf + 0.2f  * g;
            accs = 0.95f * accs + 0.05f * g;
            sqf[e] = accf; sqs[e] = accs;
        }
    }
    __syncthreads();
    const size_t base = (size_t)row * T_ + t0;
    const int off = t0 - ts;
    for (int i = tid; i < 2048; i += 256) {
        gate_o[base + i] = sga[off + i];
        qf_o[base + i]   = sqf[off + i];
        qs_o[base + i]   = sqs[off + i];
    }
}

// ---------------------------------------------------------------------------
// Persistent main kernel: 148 blocks x 1024 threads, 128-row tiles,
// bf16x3 + ldmatrix, weights staged once.
// ---------------------------------------------------------------------------
// smem byte offsets
#define SM_B1  0                     // 512
#define SM_B2  512                   // 512
#define SM_FSH 1024                  // feats hi  [128][24] bf16 = 6144
#define SM_FSL 7168
#define SM_W1H 13312                 // W1^T hi [128][24]
#define SM_W1L 19456
#define SM_W2H 25600                 // W2^T hi [128][136] = 34816
#define SM_W2L 60416
#define SM_H1H 95232                 // h1 hi [128][136]
#define SM_H1L 130048
#define SM_TOT 164864

__global__ void __launch_bounds__(1024, 1) mlp_kernel(
    const float* __restrict__ gaze,
    const float* __restrict__ lwx, const float* __restrict__ phx,
    const float* __restrict__ lwy, const float* __restrict__ phy,
    const float* __restrict__ gate_i, const float* __restrict__ qf_i,
    const float* __restrict__ qs_i,
    const float* __restrict__ b1, const float* __restrict__ b2,
    float* __restrict__ out)
{
    extern __shared__ char smem[];
    const uint32_t sbase = (uint32_t)__cvta_generic_to_shared(smem);
    uint32_t* fshw = reinterpret_cast<uint32_t*>(smem + SM_FSH);
    uint32_t* fslw = reinterpret_cast<uint32_t*>(smem + SM_FSL);
    uint32_t* h1hw = reinterpret_cast<uint32_t*>(smem + SM_H1H);
    uint32_t* h1lw = reinterpret_cast<uint32_t*>(smem + SM_H1L);
    float* b1s = reinterpret_cast<float*>(smem + SM_B1);
    float* b2s = reinterpret_cast<float*>(smem + SM_B2);

    const int tid = threadIdx.x;

    // ---- one-time staging ----
    {
        // W2 planes: 2176 x 16B each; W1 planes: 384 x 16B each
        for (int c = tid; c < 2176; c += 1024) {
            cpasync16(sbase + SM_W2H + c * 16, (const char*)g_w2h + c * 16);
            cpasync16(sbase + SM_W2L + c * 16, (const char*)g_w2l + c * 16);
        }
        if (tid < 384) {
            cpasync16(sbase + SM_W1H + tid * 16, (const char*)g_w1h + tid * 16);
            cpasync16(sbase + SM_W1L + tid * 16, (const char*)g_w1l + tid * 16);
        }
        asm volatile("cp.async.commit_group;");
        if (tid < 128) { b1s[tid] = b1[tid]; b2s[tid] = b2[tid]; }
        if (tid < 128) {   // K-pad cols 20..23 of feats, once
            fshw[tid * 12 + 10] = 0; fshw[tid * 12 + 11] = 0;
            fslw[tid * 12 + 10] = 0; fslw[tid * 12 + 11] = 0;
        }
        asm volatile("cp.async.wait_group 0;");
    }
    __syncthreads();

    const int lane = tid & 31, warp = tid >> 5;
    const int g  = lane >> 2, tg = lane & 3;
    const int wm = warp >> 2, wn = warp & 3;   // wm 0..7, wn 0..3

    // ldmatrix lane-address components
    const int t4  = lane >> 3;
    const int tr4 = lane & 7;
    const int r4  = (t4 & 1) * 8 + tr4;
    const int k4  = (t4 >> 1) * 16;
    const int r2  = ((lane >> 3) & 1) * 8 + tr4;
    const int rB4 = lane & 7;
    const int kB4 = t4 * 16;

    const float inv_dt = 240.0f;
    const float twopi  = 6.283185307179586f;
    const float wx0 = expf(lwx[0]), wx1 = expf(lwx[1]);
    const float wy0 = expf(lwy[0]), wy1 = expf(lwy[1]);
    const float px0 = phx[0], px1 = phx[1], py0 = phy[0], py1 = phy[1];

    for (int tile = blockIdx.x; tile < NTILES; tile += NBLK) {
        const int bIdx = tile >> 6;
        const int t0   = (tile & 63) << 7;

        // ---- features: threads 0..127, one timestep each ----
        if (tid < 128) {
            const float2* gz = reinterpret_cast<const float2*>(gaze) + (size_t)bIdx * T_;
            const int t = t0 + tid;
            const size_t idx = (size_t)bIdx * T_ + t;
            float2 xc = gz[t];
            float2 x1 = gz[max(t - 1, 0)];
            float2 x2 = gz[max(t - 2, 0)];
            float vx  = (xc.x - x1.x) * inv_dt;
            float vy  = (xc.y - x1.y) * inv_dt;
            float pvx = (x1.x - x2.x) * inv_dt;
            float pvy = (x1.y - x2.y) * inv_dt;
            float ax  = (vx - pvx) * inv_dt;
            float ay  = (vy - pvy) * inv_dt;
            float sp  = sqrtf(vx * vx + vy * vy);
            float isp = 1.0f / (sp + 1e-6f);
            float f[20];
            float s0, c0, s1, c1, u0, d0, u1, d1;
            sincosf(twopi * xc.x * wx0 + px0, &s0, &c0);
            sincosf(twopi * xc.x * wx1 + px1, &s1, &c1);
            sincosf(twopi * xc.y * wy0 + py0, &u0, &d0);
            sincosf(twopi * xc.y * wy1 + py1, &u1, &d1);
            f[0]=s0; f[1]=s1; f[2]=c0; f[3]=c1; f[4]=u0; f[5]=u1; f[6]=d0; f[7]=d1;
            f[8]=vx; f[9]=vy; f[10]=sp; f[11]=vx*isp; f[12]=vy*isp;
            f[13]=ax; f[14]=ay;
            f[15]=(vx*ax+vy*ay)*isp; f[16]=(vx*ay-vy*ax)*isp;
            f[17]=gate_i[idx]; f[18]=qf_i[idx]; f[19]=qs_i[idx];
#pragma unroll
            for (int j = 0; j < 10; j++) {
                uint32_t hi, lo;
                split2_bf16(f[2 * j], f[2 * j + 1], hi, lo);
                fshw[tid * 12 + j] = hi;
                fslw[tid * 12 + j] = lo;
            }
        }
        __syncthreads();

        // ========== Stage 1: h1 = gelu(feats @ W1 + b1) ==========
        {
            float acc1[4][4];
#pragma unroll
            for (int nt = 0; nt < 4; nt++) {
                int col = wn * 32 + nt * 8 + 2 * tg;
                acc1[nt][0] = b1s[col];  acc1[nt][1] = b1s[col + 1];
                acc1[nt][2] = b1s[col];  acc1[nt][3] = b1s[col + 1];
            }
            uint32_t A1h[6], A1l[6];
            {
                int rA = wm * 16;
                ldsm4(&A1h[0], sbase + SM_FSH + (rA + r4) * 48 + k4);
                ldsm4(&A1l[0], sbase + SM_FSL + (rA + r4) * 48 + k4);
                ldsm2(&A1h[4], sbase + SM_FSH + (rA + r2) * 48 + 32);
                ldsm2(&A1l[4], sbase + SM_FSL + (rA + r2) * 48 + 32);
            }
#pragma unroll
            for (int nt = 0; nt < 4; nt++) {
                int nB = wn * 32 + nt * 8;
                uint32_t B1h[3], B1l[3];
                ldsm2(&B1h[0], sbase + SM_W1H + (nB + tr4) * 48 + ((lane >> 3) & 1) * 16);
                ldsm2(&B1l[0], sbase + SM_W1L + (nB + tr4) * 48 + ((lane >> 3) & 1) * 16);
                ldsm1(&B1h[2], sbase + SM_W1H + (nB + tr4) * 48 + 32);
                ldsm1(&B1l[2], sbase + SM_W1L + (nB + tr4) * 48 + 32);
                mma16(acc1[nt], &A1h[0], &B1h[0]);
                mma16(acc1[nt], &A1h[0], &B1l[0]);
                mma16(acc1[nt], &A1l[0], &B1h[0]);
                mma8b(acc1[nt], &A1h[4], &B1h[2]);
                mma8b(acc1[nt], &A1h[4], &B1l[2]);
                mma8b(acc1[nt], &A1l[4], &B1h[2]);
            }
            // epilogue: gelu + split into h1 planes
#pragma unroll
            for (int nt = 0; nt < 4; nt++) {
                int row = wm * 16 + g;
                int cw  = (wn * 32 + nt * 8 + 2 * tg) >> 1;
                uint32_t hi, lo;
                split2_bf16(gelu_exact(acc1[nt][0]), gelu_exact(acc1[nt][1]), hi, lo);
                h1hw[row * 68 + cw] = hi;
                h1lw[row * 68 + cw] = lo;
                split2_bf16(gelu_exact(acc1[nt][2]), gelu_exact(acc1[nt][3]), hi, lo);
                h1hw[(row + 8) * 68 + cw] = hi;
                h1lw[(row + 8) * 68 + cw] = lo;
            }
        }
        __syncthreads();

        // ========== Stage 2: out = gelu(h1 @ W2 + b2) ==========
        {
            float acc2[4][4];
#pragma unroll
            for (int nt = 0; nt < 4; nt++) {
                int col = wn * 32 + nt * 8 + 2 * tg;
                acc2[nt][0] = b2s[col];  acc2[nt][1] = b2s[col + 1];
                acc2[nt][2] = b2s[col];  acc2[nt][3] = b2s[col + 1];
            }
#pragma unroll
            for (int kc2 = 0; kc2 < 4; kc2++) {
                uint32_t Ah[2][4], Al[2][4];
                int rA = wm * 16 + r4;
#pragma unroll
                for (int s = 0; s < 2; s++) {
                    ldsm4(Ah[s], sbase + SM_H1H + rA * 272 + kc2 * 64 + s * 32 + k4);
                    ldsm4(Al[s], sbase + SM_H1L + rA * 272 + kc2 * 64 + s * 32 + k4);
                }
#pragma unroll
                for (int nt = 0; nt < 4; nt++) {
                    uint32_t Bh[4], Bl[4];
                    int nB = wn * 32 + nt * 8 + rB4;
                    ldsm4(Bh, sbase + SM_W2H + nB * 272 + kc2 * 64 + kB4);
                    ldsm4(Bl, sbase + SM_W2L + nB * 272 + kc2 * 64 + kB4);
#pragma unroll
                    for (int s = 0; s < 2; s++) {
                        mma16(acc2[nt], Ah[s], &Bh[2 * s]);
                        mma16(acc2[nt], Ah[s], &Bl[2 * s]);
                        mma16(acc2[nt], Al[s], &Bh[2 * s]);
                    }
                }
            }
            // final epilogue
            const size_t r0 = (size_t)tile * 128;
#pragma unroll
            for (int nt = 0; nt < 4; nt++) {
                int r = wm * 16 + g;
                int c = wn * 32 + nt * 8 + 2 * tg;
                float2 v0 = make_float2(gelu_exact(acc2[nt][0]), gelu_exact(acc2[nt][1]));
                float2 v1 = make_float2(gelu_exact(acc2[nt][2]), gelu_exact(acc2[nt][3]));
                *reinterpret_cast<float2*>(out + (r0 + r) * 128 + c)     = v0;
                *reinterpret_cast<float2*>(out + (r0 + r + 8) * 128 + c) = v1;
            }
        }
        __syncthreads();
    }
}

// ---------------------------------------------------------------------------
extern "C" void kernel_launch(void* const* d_in, const int* in_sizes, int n_in,
                              void* d_out, int out_size)
{
    const float* gaze   = (const float*)d_in[0];
    const float* lwx    = (const float*)d_in[1];
    const float* phx    = (const float*)d_in[2];
    const float* lwy    = (const float*)d_in[3];
    const float* phy    = (const float*)d_in[4];
    const float* logthr = (const float*)d_in[5];
    const float* invT   = (const float*)d_in[6];
    const float* W1     = (const float*)d_in[7];
    const float* b1     = (const float*)d_in[8];
    const float* W2     = (const float*)d_in[9];
    const float* b2     = (const float*)d_in[10];
    float* out = (float*)d_out;

    float *gate, *qf, *qs;
    cudaGetSymbolAddress((void**)&gate, g_gate);
    cudaGetSymbolAddress((void**)&qf,   g_qf);
    cudaGetSymbolAddress((void**)&qs,   g_qs);

    const size_t smemA = (size_t)(5124 + 3 * 2560 + 32) * sizeof(float);
    cudaFuncSetAttribute(ema_kernel,
                         cudaFuncAttributeMaxDynamicSharedMemorySize, (int)smemA);
    ema_kernel<<<B_ * 4, 256, smemA>>>(gaze, logthr, invT, W1, W2, gate, qf, qs);

    cudaFuncSetAttribute(mlp_kernel,
                         cudaFuncAttributeMaxDynamicSharedMemorySize, SM_TOT);
    mlp_kernel<<<NBLK, 1024, SM_TOT>>>(
        gaze, lwx, phx, lwy, phy, gate, qf, qs, b1, b2, out);
}

// round 9
// speedup vs baseline: 1.0815x; 1.0815x over previous
#include <cuda_runtime.h>
#include <cuda_bf16.h>
#include <stdint.h>
#include <math.h>

#define B_    64
#define T_    8192
#define DIN   20
#define NROWS ((size_t)B_ * T_)
#define WARM  512
#define NTILES 4096
#define NBLK   148

// device scratch
__device__ float g_gate[NROWS];
__device__ float g_qf[NROWS];
__device__ float g_qs[NROWS];
// pre-split weight planes (bf16 hi/lo)
__device__ __align__(16) __nv_bfloat16 g_w1h[128 * 24];
__device__ __align__(16) __nv_bfloat16 g_w1l[128 * 24];
__device__ __align__(16) __nv_bfloat16 g_w2h[128 * 136];
__device__ __align__(16) __nv_bfloat16 g_w2l[128 * 136];

// ---------------------------------------------------------------------------
__device__ __forceinline__ void mma16(float* d, const uint32_t* a, const uint32_t* b) {
    asm volatile(
        "mma.sync.aligned.m16n8k16.row.col.f32.bf16.bf16.f32 "
        "{%0,%1,%2,%3}, {%4,%5,%6,%7}, {%8,%9}, {%0,%1,%2,%3};"
        : "+f"(d[0]), "+f"(d[1]), "+f"(d[2]), "+f"(d[3])
        : "r"(a[0]), "r"(a[1]), "r"(a[2]), "r"(a[3]), "r"(b[0]), "r"(b[1]));
}
__device__ __forceinline__ void mma8b(float* d, const uint32_t* a, const uint32_t* b) {
    asm volatile(
        "mma.sync.aligned.m16n8k8.row.col.f32.bf16.bf16.f32 "
        "{%0,%1,%2,%3}, {%4,%5}, {%6}, {%0,%1,%2,%3};"
        : "+f"(d[0]), "+f"(d[1]), "+f"(d[2]), "+f"(d[3])
        : "r"(a[0]), "r"(a[1]), "r"(b[0]));
}
__device__ __forceinline__ void ldsm4(uint32_t* R, uint32_t addr) {
    asm volatile("ldmatrix.sync.aligned.m8n8.x4.shared.b16 {%0,%1,%2,%3},[%4];"
        : "=r"(R[0]), "=r"(R[1]), "=r"(R[2]), "=r"(R[3]) : "r"(addr));
}
__device__ __forceinline__ void ldsm2(uint32_t* R, uint32_t addr) {
    asm volatile("ldmatrix.sync.aligned.m8n8.x2.shared.b16 {%0,%1},[%2];"
        : "=r"(R[0]), "=r"(R[1]) : "r"(addr));
}
__device__ __forceinline__ void ldsm1(uint32_t* R, uint32_t addr) {
    asm volatile("ldmatrix.sync.aligned.m8n8.x1.shared.b16 {%0},[%1];"
        : "=r"(R[0]) : "r"(addr));
}
__device__ __forceinline__ void cpasync16(uint32_t saddr, const void* g) {
    asm volatile("cp.async.cg.shared.global [%0], [%1], 16;" :: "r"(saddr), "l"(g));
}
__device__ __forceinline__ float gelu_exact(float x) {
    return 0.5f * x * (1.0f + erff(x * 0.70710678118654752f));
}
__device__ __forceinline__ void split2_bf16(float x0, float x1,
                                            uint32_t& hi, uint32_t& lo) {
    uint32_t h;
    asm("cvt.rn.bf16x2.f32 %0, %1, %2;" : "=r"(h) : "f"(x1), "f"(x0));
    float h0 = __uint_as_float(h << 16);
    float h1 = __uint_as_float(h & 0xffff0000u);
    float r0 = x0 - h0, r1 = x1 - h1;
    asm("cvt.rn.bf16x2.f32 %0, %1, %2;" : "=r"(lo) : "f"(r1), "f"(r0));
    hi = h;
}

// ---------------------------------------------------------------------------
// Kernel A: gate + EMA + folded weight pre-split.
// ---------------------------------------------------------------------------
__global__ void __launch_bounds__(256) ema_kernel(
    const float* __restrict__ gaze,
    const float* __restrict__ p_logthr, const float* __restrict__ p_invT,
    const float* __restrict__ W1, const float* __restrict__ W2,
    float* __restrict__ gate_o, float* __restrict__ qf_o, float* __restrict__ qs_o)
{
    extern __shared__ float sm[];
    float2* sg  = reinterpret_cast<float2*>(sm);
    float*  sga = sm + 5124;
    float*  sqf = sga + 2560;
    float*  sqs = sqf + 2560;
    float*  scn = sqs + 2560;

    const int tid = threadIdx.x;

    {   // weight prep
        int i = blockIdx.x * 256 + tid;
        if (i < 128 * 136) {
            int n = i / 136, k = i - n * 136;
            float v = (k < 128) ? W2[k * 128 + n] : 0.0f;
            __nv_bfloat16 h = __float2bfloat16_rn(v);
            g_w2h[i] = h;
            g_w2l[i] = __float2bfloat16_rn(v - __bfloat162float(h));
        }
        if (i < 128 * 24) {
            int n = i / 24, k = i - n * 24;
            float v = (k < DIN) ? W1[k * 128 + n] : 0.0f;
            __nv_bfloat16 h = __float2bfloat16_rn(v);
            g_w1h[i] = h;
            g_w1l[i] = __float2bfloat16_rn(v - __bfloat162float(h));
        }
    }

    const int row = blockIdx.x >> 2;
    const int t0  = (blockIdx.x & 3) * 2048;
    const int ts  = max(t0 - WARM, 0);
    const int ts2 = max(ts - 1, 0);
    const int E   = t0 + 2048 - ts;
    const int NG  = t0 + 2048 - ts2;
    const int hof = ts - ts2;

    const float2* gz = reinterpret_cast<const float2*>(gaze) + (size_t)row * T_;
    for (int i = tid; i < NG; i += 256) sg[i] = gz[ts2 + i];
    const float thr  = expf(p_logthr[0]);
    const float invT = p_invT[0];
    const float inv_dt = 240.0f;
    __syncthreads();

    const int CH = (E + 255) >> 8;
    float Af = 1.0f, Bf = 0.0f, As = 1.0f, Bs = 0.0f;
    for (int i = 0; i < CH; i++) {
        int e = tid * CH + i;
        if (e < E) {
            int j = e + hof;
            float2 xc = sg[j];
            float2 x1 = sg[max(j - 1, 0)];
            float vx = (xc.x - x1.x) * inv_dt;
            float vy = (xc.y - x1.y) * inv_dt;
            float sp = sqrtf(vx * vx + vy * vy);
            float g  = 1.0f / (1.0f + expf(-invT * (sp - thr)));
            sga[e] = g;
            Bf = 0.8f  * Bf + 0.2f  * g;  Af *= 0.8f;
            Bs = 0.95f * Bs + 0.05f * g;  As *= 0.95f;
        }
    }
    const unsigned full = 0xffffffffu;
    const int lane = tid & 31, warp = tid >> 5;
    float iAf = Af, iBf = Bf, iAs = As, iBs = Bs;
#pragma unroll
    for (int d = 1; d < 32; d <<= 1) {
        float pa = __shfl_up_sync(full, iAf, d);
        float pb = __shfl_up_sync(full, iBf, d);
        float qa = __shfl_up_sync(full, iAs, d);
        float qb = __shfl_up_sync(full, iBs, d);
        if (lane >= d) {
            iBf = iAf * pb + iBf;  iAf *= pa;
            iBs = iAs * qb + iBs;  iAs *= qa;
        }
    }
    float eAf = __shfl_up_sync(full, iAf, 1), eBf = __shfl_up_sync(full, iBf, 1);
    float eAs = __shfl_up_sync(full, iAs, 1), eBs = __shfl_up_sync(full, iBs, 1);
    if (lane == 0) { eAf = 1.0f; eBf = 0.0f; eAs = 1.0f; eBs = 0.0f; }
    if (lane == 31) {
        scn[warp] = iAf; scn[8 + warp] = iBf; scn[16 + warp] = iAs; scn[24 + warp] = iBs;
    }
    __syncthreads();
    float pBf = 0.0f, pBs = 0.0f;
    for (int w = 0; w < warp; w++) {
        pBf = scn[w] * pBf + scn[8 + w];
        pBs = scn[16 + w] * pBs + scn[24 + w];
    }
    float accf = eAf * pBf + eBf;
    float accs = eAs * pBs + eBs;
    for (int i = 0; i < CH; i++) {
        int e = tid * CH + i;
        if (e < E) {
            float g = sga[e];
            accf = 0.8f  * accf + 0.2f  * g;
            accs = 0.95f * accs + 0.05f * g;
            sqf[e] = accf; sqs[e] = accs;
        }
    }
    __syncthreads();
    const size_t base = (size_t)row * T_ + t0;
    const int off = t0 - ts;
    for (int i = tid; i < 2048; i += 256) {
        gate_o[base + i] = sga[off + i];
        qf_o[base + i]   = sqf[off + i];
        qs_o[base + i]   = sqs[off + i];
    }
}

// ---------------------------------------------------------------------------
// Persistent main kernel: 148 blocks x 512 threads (16 warps), 128-row tiles,
// warp tile 32x32, bf16x3 + ldmatrix, weights staged once.
// ---------------------------------------------------------------------------
// smem byte offsets
#define SM_FSH 0                     // feats hi [128][24] bf16 = 6144
#define SM_FSL 6144
#define SM_W1H 12288                 // W1^T hi [128][24]
#define SM_W1L 18432
#define SM_W2H 24576                 // W2^T hi [128][136] = 34816
#define SM_W2L 59392
#define SM_H1H 94208                 // h1 hi [128][136]
#define SM_H1L 129024
#define SM_B1  163840                // 512
#define SM_B2  164352                // 512
#define SM_TOT 164864

__global__ void __launch_bounds__(512, 1) mlp_kernel(
    const float* __restrict__ gaze,
    const float* __restrict__ lwx, const float* __restrict__ phx,
    const float* __restrict__ lwy, const float* __restrict__ phy,
    const float* __restrict__ gate_i, const float* __restrict__ qf_i,
    const float* __restrict__ qs_i,
    const float* __restrict__ b1, const float* __restrict__ b2,
    float* __restrict__ out)
{
    extern __shared__ char smem[];
    const uint32_t sbase = (uint32_t)__cvta_generic_to_shared(smem);
    uint32_t* fshw = reinterpret_cast<uint32_t*>(smem + SM_FSH);
    uint32_t* fslw = reinterpret_cast<uint32_t*>(smem + SM_FSL);
    uint32_t* h1hw = reinterpret_cast<uint32_t*>(smem + SM_H1H);
    uint32_t* h1lw = reinterpret_cast<uint32_t*>(smem + SM_H1L);
    float* b1s = reinterpret_cast<float*>(smem + SM_B1);
    float* b2s = reinterpret_cast<float*>(smem + SM_B2);

    const int tid = threadIdx.x;

    // ---- one-time staging ----
    for (int c = tid; c < 2176; c += 512) {
        cpasync16(sbase + SM_W2H + c * 16, (const char*)g_w2h + c * 16);
        cpasync16(sbase + SM_W2L + c * 16, (const char*)g_w2l + c * 16);
    }
    if (tid < 384) {
        cpasync16(sbase + SM_W1H + tid * 16, (const char*)g_w1h + tid * 16);
        cpasync16(sbase + SM_W1L + tid * 16, (const char*)g_w1l + tid * 16);
    }
    asm volatile("cp.async.commit_group;");
    if (tid < 128) {
        b1s[tid] = b1[tid]; b2s[tid] = b2[tid];
        // K-pad cols 20..23 of feats planes (constant zero)
        fshw[tid * 12 + 10] = 0; fshw[tid * 12 + 11] = 0;
        fslw[tid * 12 + 10] = 0; fslw[tid * 12 + 11] = 0;
    }
    asm volatile("cp.async.wait_group 0;");
    __syncthreads();

    const int lane = tid & 31, warp = tid >> 5;
    const int g  = lane >> 2, tg = lane & 3;
    const int wm = warp >> 2, wn = warp & 3;

    // ldmatrix lane-address components
    const int t4  = lane >> 3;
    const int tr4 = lane & 7;
    const int r4  = (t4 & 1) * 8 + tr4;
    const int k4  = (t4 >> 1) * 16;
    const int r2  = ((lane >> 3) & 1) * 8 + tr4;
    const int rB4 = lane & 7;
    const int kB4 = t4 * 16;

    const float inv_dt = 240.0f;
    const float twopi  = 6.283185307179586f;
    const float wx0 = expf(lwx[0]), wx1 = expf(lwx[1]);
    const float wy0 = expf(lwy[0]), wy1 = expf(lwy[1]);
    const float px0 = phx[0], px1 = phx[1], py0 = phy[0], py1 = phy[1];

    for (int tile = blockIdx.x; tile < NTILES; tile += NBLK) {
        const int bIdx = tile >> 6;
        const int t0   = (tile & 63) << 7;

        // ---- features: 256 threads, 2 per row ----
        if (tid < 256) {
            const int row = tid >> 1, sub = tid & 1;
            const float2* gz = reinterpret_cast<const float2*>(gaze) + (size_t)bIdx * T_;
            const int t = t0 + row;
            const size_t idx = (size_t)bIdx * T_ + t;
            float2 xc = gz[t];
            float2 x1 = gz[max(t - 1, 0)];
            float2 x2 = gz[max(t - 2, 0)];
            float vx  = (xc.x - x1.x) * inv_dt;
            float vy  = (xc.y - x1.y) * inv_dt;
            float ax  = (vx - (x1.x - x2.x) * inv_dt) * inv_dt;
            float ay  = (vy - (x1.y - x2.y) * inv_dt) * inv_dt;
            float sp  = sqrtf(vx * vx + vy * vy);
            float isp = 1.0f / (sp + 1e-6f);
            uint32_t hi, lo;
            if (sub == 0) {
                float s0, c0, s1, c1;
                sincosf(twopi * xc.x * wx0 + px0, &s0, &c0);
                sincosf(twopi * xc.x * wx1 + px1, &s1, &c1);
                split2_bf16(s0, s1, hi, lo); fshw[row*12+0] = hi; fslw[row*12+0] = lo;
                split2_bf16(c0, c1, hi, lo); fshw[row*12+1] = hi; fslw[row*12+1] = lo;
                split2_bf16(vx, vy, hi, lo); fshw[row*12+4] = hi; fslw[row*12+4] = lo;
                split2_bf16(sp, vx*isp, hi, lo); fshw[row*12+5] = hi; fslw[row*12+5] = lo;
            } else {
                float u0, d0, u1, d1;
                sincosf(twopi * xc.y * wy0 + py0, &u0, &d0);
                sincosf(twopi * xc.y * wy1 + py1, &u1, &d1);
                float gate = gate_i[idx], qf = qf_i[idx], qs = qs_i[idx];
                split2_bf16(u0, u1, hi, lo); fshw[row*12+2] = hi; fslw[row*12+2] = lo;
                split2_bf16(d0, d1, hi, lo); fshw[row*12+3] = hi; fslw[row*12+3] = lo;
                split2_bf16(vy*isp, ax, hi, lo); fshw[row*12+6] = hi; fslw[row*12+6] = lo;
                split2_bf16(ay, (vx*ax+vy*ay)*isp, hi, lo); fshw[row*12+7] = hi; fslw[row*12+7] = lo;
                split2_bf16((vx*ay-vy*ax)*isp, gate, hi, lo); fshw[row*12+8] = hi; fslw[row*12+8] = lo;
                split2_bf16(qf, qs, hi, lo); fshw[row*12+9] = hi; fslw[row*12+9] = lo;
            }
        }
        __syncthreads();

        // ========== Stage 1: h1 = gelu(feats @ W1 + b1) ==========
#pragma unroll
        for (int mt = 0; mt < 2; mt++) {
            const int rA = wm * 32 + mt * 16;
            uint32_t A1h[6], A1l[6];
            ldsm4(&A1h[0], sbase + SM_FSH + (rA + r4) * 48 + k4);
            ldsm4(&A1l[0], sbase + SM_FSL + (rA + r4) * 48 + k4);
            ldsm2(&A1h[4], sbase + SM_FSH + (rA + r2) * 48 + 32);
            ldsm2(&A1l[4], sbase + SM_FSL + (rA + r2) * 48 + 32);
            float acc1[4][4];
#pragma unroll
            for (int nt = 0; nt < 4; nt++) {
                int col = wn * 32 + nt * 8 + 2 * tg;
                acc1[nt][0] = b1s[col];  acc1[nt][1] = b1s[col + 1];
                acc1[nt][2] = acc1[nt][0];  acc1[nt][3] = acc1[nt][1];
                int nB = wn * 32 + nt * 8;
                uint32_t B1h[3], B1l[3];
                ldsm2(&B1h[0], sbase + SM_W1H + (nB + tr4) * 48 + ((lane >> 3) & 1) * 16);
                ldsm2(&B1l[0], sbase + SM_W1L + (nB + tr4) * 48 + ((lane >> 3) & 1) * 16);
                ldsm1(&B1h[2], sbase + SM_W1H + (nB + tr4) * 48 + 32);
                ldsm1(&B1l[2], sbase + SM_W1L + (nB + tr4) * 48 + 32);
                mma16(acc1[nt], &A1h[0], &B1h[0]);
                mma16(acc1[nt], &A1h[0], &B1l[0]);
                mma16(acc1[nt], &A1l[0], &B1h[0]);
                mma8b(acc1[nt], &A1h[4], &B1h[2]);
                mma8b(acc1[nt], &A1h[4], &B1l[2]);
                mma8b(acc1[nt], &A1l[4], &B1h[2]);
            }
#pragma unroll
            for (int nt = 0; nt < 4; nt++) {
                int row = rA + g;
                int cw  = (wn * 32 + nt * 8 + 2 * tg) >> 1;
                uint32_t hi, lo;
                split2_bf16(gelu_exact(acc1[nt][0]), gelu_exact(acc1[nt][1]), hi, lo);
                h1hw[row * 68 + cw] = hi;
                h1lw[row * 68 + cw] = lo;
                split2_bf16(gelu_exact(acc1[nt][2]), gelu_exact(acc1[nt][3]), hi, lo);
                h1hw[(row + 8) * 68 + cw] = hi;
                h1lw[(row + 8) * 68 + cw] = lo;
            }
        }
        __syncthreads();

        // ========== Stage 2: out = gelu(h1 @ W2 + b2) ==========
        {
            float acc2[2][4][4];
#pragma unroll
            for (int mt = 0; mt < 2; mt++)
#pragma unroll
                for (int nt = 0; nt < 4; nt++) {
                    int col = wn * 32 + nt * 8 + 2 * tg;
                    acc2[mt][nt][0] = b2s[col];  acc2[mt][nt][1] = b2s[col + 1];
                    acc2[mt][nt][2] = acc2[mt][nt][0];
                    acc2[mt][nt][3] = acc2[mt][nt][1];
                }
#pragma unroll
            for (int kc2 = 0; kc2 < 4; kc2++) {
                uint32_t Ah[2][2][4], Al[2][2][4];
#pragma unroll
                for (int mt = 0; mt < 2; mt++) {
                    int rA = wm * 32 + mt * 16 + r4;
#pragma unroll
                    for (int s = 0; s < 2; s++) {
                        ldsm4(Ah[mt][s], sbase + SM_H1H + rA * 272 + kc2 * 64 + s * 32 + k4);
                        ldsm4(Al[mt][s], sbase + SM_H1L + rA * 272 + kc2 * 64 + s * 32 + k4);
                    }
                }
#pragma unroll
                for (int nt = 0; nt < 4; nt++) {
                    uint32_t Bh[4], Bl[4];
                    int nB = wn * 32 + nt * 8 + rB4;
                    ldsm4(Bh, sbase + SM_W2H + nB * 272 + kc2 * 64 + kB4);
                    ldsm4(Bl, sbase + SM_W2L + nB * 272 + kc2 * 64 + kB4);
#pragma unroll
                    for (int mt = 0; mt < 2; mt++)
#pragma unroll
                        for (int s = 0; s < 2; s++) {
                            mma16(acc2[mt][nt], Ah[mt][s], &Bh[2 * s]);
                            mma16(acc2[mt][nt], Ah[mt][s], &Bl[2 * s]);
                            mma16(acc2[mt][nt], Al[mt][s], &Bh[2 * s]);
                        }
                }
            }
            const size_t r0 = (size_t)tile * 128;
#pragma unroll
            for (int mt = 0; mt < 2; mt++)
#pragma unroll
                for (int nt = 0; nt < 4; nt++) {
                    int r = wm * 32 + mt * 16 + g;
                    int c = wn * 32 + nt * 8 + 2 * tg;
                    float2 v0 = make_float2(gelu_exact(acc2[mt][nt][0]), gelu_exact(acc2[mt][nt][1]));
                    float2 v1 = make_float2(gelu_exact(acc2[mt][nt][2]), gelu_exact(acc2[mt][nt][3]));
                    *reinterpret_cast<float2*>(out + (r0 + r) * 128 + c)     = v0;
                    *reinterpret_cast<float2*>(out + (r0 + r + 8) * 128 + c) = v1;
                }
        }
        __syncthreads();
    }
}

// ---------------------------------------------------------------------------
extern "C" void kernel_launch(void* const* d_in, const int* in_sizes, int n_in,
                              void* d_out, int out_size)
{
    const float* gaze   = (const float*)d_in[0];
    const float* lwx    = (const float*)d_in[1];
    const float* phx    = (const float*)d_in[2];
    const float* lwy    = (const float*)d_in[3];
    const float* phy    = (const float*)d_in[4];
    const float* logthr = (const float*)d_in[5];
    const float* invT   = (const float*)d_in[6];
    const float* W1     = (const float*)d_in[7];
    const float* b1     = (const float*)d_in[8];
    const float* W2     = (const float*)d_in[9];
    const float* b2     = (const float*)d_in[10];
    float* out = (float*)d_out;

    float *gate, *qf, *qs;
    cudaGetSymbolAddress((void**)&gate, g_gate);
    cudaGetSymbolAddress((void**)&qf,   g_qf);
    cudaGetSymbolAddress((void**)&qs,   g_qs);

    const size_t smemA = (size_t)(5124 + 3 * 2560 + 32) * sizeof(float);
    cudaFuncSetAttribute(ema_kernel,
                         cudaFuncAttributeMaxDynamicSharedMemorySize, (int)smemA);
    ema_kernel<<<B_ * 4, 256, smemA>>>(gaze, logthr, invT, W1, W2, gate, qf, qs);

    cudaFuncSetAttribute(mlp_kernel,
                         cudaFuncAttributeMaxDynamicSharedMemorySize, SM_TOT);
    mlp_kernel<<<NBLK, 512, SM_TOT>>>(
        gaze, lwx, phx, lwy, phy, gate, qf, qs, b1, b2, out);
}